// round 7
// baseline (speedup 1.0000x reference)
#include <cuda_runtime.h>
#include <math.h>

// Problem constants
#define NB 8
#define NK 1024
#define NL 1024
#define ND 1024
#define NO 6
#define NE 128

// Scratch (tiny): everything l-independent
__device__ __align__(16) float g_S [NB*NO*NE];   // raw vote sum   [b,o,e]
__device__ __align__(16) float g_Wv[NB*NO*ND];   // W @ v          [b,o,d]
__device__ __align__(16) float g_a [NB*NK*NO];   // logits         [b,k,o]
__device__ __align__(16) float g_p [NB*NK*NO];   // probs          [b,k,o]
__device__ __align__(16) float g_pu[NB*NO*ND];   // p^T @ u        [b,o,d]
__device__ int g_mask_is_u8;                     // mask dtype flag

// ---------------------------------------------------------------------------
// Prolog: zero g_pu & g_S, detect mask dtype.
// If mask is int32 (LE), bytes at i%4!=0 over the first 256 bytes are all
// zero (values 0/1). If uint8 0/1 mask, ~half of them are nonzero.
__global__ void k_prolog(const unsigned char* __restrict__ mraw) {
    int i = blockIdx.x * 256 + threadIdx.x;
    if (i < NB*NO*ND) g_pu[i] = 0.f;
    if (i < NB*NO*NE) g_S[i]  = 0.f;
    if (blockIdx.x == 0 && threadIdx.x == 0) {
        int u8 = 0;
        for (int j = 0; j < 256; j++)
            if ((j & 3) != 0 && mraw[j] != 0) u8 = 1;
        g_mask_is_u8 = u8;
    }
}

__device__ __forceinline__ int mask_at(const unsigned char* mraw, size_t idx) {
    if (g_mask_is_u8) return mraw[idx] != 0;
    return ((const int*)mraw)[idx] != 0;
}

// ---------------------------------------------------------------------------
// Iteration-0 shortcut: p0 = 1/6 uniformly, so pu0[b,o,d] = (1/6)*sum_k u —
// o-independent. Compute colsum into g_pu[b][o=0][:].
// grid (NB, ND/256, 16), block 256
__global__ void k_colsum(const float* __restrict__ u) {
    int b  = blockIdx.x;
    int d  = blockIdx.y * 256 + threadIdx.x;
    int kb = blockIdx.z * 64;
    const float* up = u + ((size_t)b * NK + kb) * ND + d;
    float acc = 0.f;
#pragma unroll 8
    for (int kk = 0; kk < 64; kk++) acc += up[(size_t)kk * ND];
    atomicAdd(&g_pu[(size_t)b * NO * ND + d], acc);
}

// ---------------------------------------------------------------------------
// S[b,o,e] += sum_{d in 16-chunk} pu[b,o,d] * W[o,d,e] for all 8 b at once.
// FIRST: read o-independent colsum (o=0 row) scaled by 1/6.
// grid (NO, ND/16), block 128.
template <int FIRST>
__global__ void k_S(const float* __restrict__ W) {
    __shared__ float spu[NB][16];
    int o  = blockIdx.x;
    int dc = blockIdx.y * 16;
    int e  = threadIdx.x;

    {   // 128 threads load exactly 128 entries
        int b = threadIdx.x >> 4, dd = threadIdx.x & 15;
        float v = FIRST ? g_pu[(size_t)b * NO * ND + dc + dd] * (1.f / 6.f)
                        : g_pu[((size_t)b * NO + o) * ND + dc + dd];
        spu[b][dd] = v;
    }
    __syncthreads();

    float acc[NB];
#pragma unroll
    for (int b = 0; b < NB; b++) acc[b] = 0.f;

    const float* Wo = W + ((size_t)o * ND + dc) * NE + e;
#pragma unroll
    for (int dd = 0; dd < 16; dd++) {
        float w = Wo[(size_t)dd * NE];
#pragma unroll
        for (int b = 0; b < NB; b++) acc[b] += spu[b][dd] * w;
    }
#pragma unroll
    for (int b = 0; b < NB; b++)
        atomicAdd(&g_S[((size_t)b * NO + o) * NE + e], acc[b]);
}

// ---------------------------------------------------------------------------
// Fused squash + Wv, shuffle-free smem-tile version.
// v = squash(S) (redundant per block, cheap); Wv[b,o,d] = sum_e W[o,d,e]*v[b,o,e].
// Each thread owns one d and two b's; full e-dot in registers.
// Also zeroes g_pu for the next k_apu's atomics (96 blocks x 512 floats).
// grid (NO, ND/64), block 256.
__global__ void k_WvSq(const float* __restrict__ W) {
    __shared__ float sW[64][NE + 1];  // stride 129 -> conflict-free
    __shared__ float sv[NB][NE];
    __shared__ float sfac[NB];
    int o  = blockIdx.x;
    int db = blockIdx.y * 64;
    int wid = threadIdx.x >> 5, lane = threadIdx.x & 31;

    // zero g_pu slice: 49152 / 96 blocks = 512 floats per block
    {
        int slice = blockIdx.x * (ND / 64) + blockIdx.y;   // 0..95
        ((float2*)g_pu)[slice * 256 + threadIdx.x] = make_float2(0.f, 0.f);
    }

    // stage W tile [64 d][128 e] (coalesced)
    for (int i = threadIdx.x; i < 64 * NE; i += 256) {
        int d = i >> 7, e = i & 127;
        sW[d][e] = W[((size_t)o * ND + db + d) * NE + e];
    }
    // stage S
    for (int i = threadIdx.x; i < NB * NE; i += 256)
        sv[i >> 7][i & 127] = g_S[((size_t)(i >> 7) * NO + o) * NE + (i & 127)];
    __syncthreads();

    // squash factor, warp w -> b=w
    {
        float sq = 0.f;
#pragma unroll
        for (int j = 0; j < 4; j++) {
            float x = sv[wid][lane + 32 * j];
            sq += x * x;
        }
#pragma unroll
        for (int off = 16; off; off >>= 1) sq += __shfl_xor_sync(0xffffffffu, sq, off);
        if (lane == 0) sfac[wid] = sq / (1.f + sq) / (sqrtf(sq) + 1e-8f);
    }
    __syncthreads();
    for (int i = threadIdx.x; i < NB * NE; i += 256)
        sv[i >> 7][i & 127] *= sfac[i >> 7];
    __syncthreads();

    // thread -> (d = tid&63, b = tid>>6 and b+4)
    int d  = threadIdx.x & 63;
    int b0 = threadIdx.x >> 6;        // 0..3
    float acc0 = 0.f, acc1 = 0.f;
#pragma unroll 4
    for (int e = 0; e < NE; e++) {
        float w = sW[d][e];
        acc0 += w * sv[b0][e];
        acc1 += w * sv[b0 + 4][e];
    }
    g_Wv[((size_t)b0 * NO + o) * ND + db + d]       = acc0;
    g_Wv[((size_t)(b0 + 4) * NO + o) * ND + db + d] = acc1;
}

// ---------------------------------------------------------------------------
// Fused agreement + softmax + pu-accumulation:
//  phase 1: a[b,k,o] (+)= sum_d u[b,k,d]*Wv[b,o,d]; p = masked softmax (->smem+g_p)
//  phase 2: pu[b,o,d] += sum_{k in block} p[k,o]*u[b,k,d]  (u rows hot in L1/L2)
// Also zeroes g_S slices for the next k_S.
// grid (NB, NK/32), block 256 = 8 warps, each warp does 4 k's.
template <int ACCUM>
__global__ void k_apu(const float* __restrict__ u,
                      const unsigned char* __restrict__ mraw) {
    __shared__ float sWv[NO * ND];  // 24 KB
    __shared__ float sp[32][NO];
    int b  = blockIdx.x;
    int kb = blockIdx.y * 32;

    // zero g_S slice: 6144 / 256 blocks = 24 floats each
    {
        int slice = blockIdx.x * 32 + blockIdx.y;   // 0..255
        if (threadIdx.x < 24) g_S[(size_t)slice * 24 + threadIdx.x] = 0.f;
    }

    for (int i = threadIdx.x; i < NO * ND; i += 256)
        sWv[i] = g_Wv[(size_t)b * NO * ND + i];
    __syncthreads();

    int warp = threadIdx.x >> 5, lane = threadIdx.x & 31;

    for (int ki = 0; ki < 4; ki++) {
        int k = kb + warp * 4 + ki;
        const float* urow = u + ((size_t)b * NK + k) * ND;
        float a0 = 0, a1 = 0, a2 = 0, a3 = 0, a4 = 0, a5 = 0;
#pragma unroll 4
        for (int j = 0; j < 32; j++) {
            int d = lane + 32 * j;
            float uv = urow[d];
            a0 += uv * sWv[d];
            a1 += uv * sWv[ND + d];
            a2 += uv * sWv[2 * ND + d];
            a3 += uv * sWv[3 * ND + d];
            a4 += uv * sWv[4 * ND + d];
            a5 += uv * sWv[5 * ND + d];
        }
#pragma unroll
        for (int off = 16; off; off >>= 1) {
            a0 += __shfl_xor_sync(0xffffffffu, a0, off);
            a1 += __shfl_xor_sync(0xffffffffu, a1, off);
            a2 += __shfl_xor_sync(0xffffffffu, a2, off);
            a3 += __shfl_xor_sync(0xffffffffu, a3, off);
            a4 += __shfl_xor_sync(0xffffffffu, a4, off);
            a5 += __shfl_xor_sync(0xffffffffu, a5, off);
        }
        if (lane == 0) {
            float av[NO] = {a0, a1, a2, a3, a4, a5};
            size_t base = ((size_t)b * NK + k) * NO;
            if (ACCUM) {
#pragma unroll
                for (int o = 0; o < NO; o++) av[o] += g_a[base + o];
            }
#pragma unroll
            for (int o = 0; o < NO; o++) g_a[base + o] = av[o];

            float pr[NO];
            if (mask_at(mraw, (size_t)b * NK + k)) {
#pragma unroll
                for (int o = 0; o < NO; o++) pr[o] = 1.f / 6.f;
            } else {
                float m = av[0];
#pragma unroll
                for (int o = 1; o < NO; o++) m = fmaxf(m, av[o]);
                float ssum = 0.f;
#pragma unroll
                for (int o = 0; o < NO; o++) { pr[o] = expf(av[o] - m); ssum += pr[o]; }
                float inv = 1.f / ssum;
#pragma unroll
                for (int o = 0; o < NO; o++) pr[o] *= inv;
            }
#pragma unroll
            for (int o = 0; o < NO; o++) {
                g_p[base + o] = pr[o];
                sp[warp * 4 + ki][o] = pr[o];
            }
        }
    }
    __syncthreads();

    // phase 2: pu accumulation over this block's 32 k rows
#pragma unroll
    for (int dj = 0; dj < 4; dj++) {
        int d = dj * 256 + threadIdx.x;
        const float* ucol = u + ((size_t)b * NK + kb) * ND + d;
        float acc[NO];
#pragma unroll
        for (int o = 0; o < NO; o++) acc[o] = 0.f;
#pragma unroll 4
        for (int kk = 0; kk < 32; kk++) {
            float uv = ucol[(size_t)kk * ND];
#pragma unroll
            for (int o = 0; o < NO; o++) acc[o] += sp[kk][o] * uv;
        }
#pragma unroll
        for (int o = 0; o < NO; o++)
            atomicAdd(&g_pu[((size_t)b * NO + o) * ND + d], acc[o]);
    }
}

// ---------------------------------------------------------------------------
// Final: squash(S) fused with the L-broadcast of outputs_v.
// outputs_v[b,l,o,e] = squash(S)[b,o,e].  grid (NB, NL/64), block 256
__global__ void k_out_v(float4* __restrict__ out) {
    __shared__ __align__(16) float sv[NO * NE];  // 768 floats
    __shared__ float sfac[NO];
    int b  = blockIdx.x;
    int lb = blockIdx.y * 64;
    int wid = threadIdx.x >> 5, lane = threadIdx.x & 31;

    for (int i = threadIdx.x; i < NO * NE; i += 256)
        sv[i] = g_S[(size_t)b * NO * NE + i];
    __syncthreads();

    if (wid < NO) {
        float sq = 0.f;
#pragma unroll
        for (int j = 0; j < 4; j++) {
            float x = sv[wid * NE + lane + 32 * j];
            sq += x * x;
        }
#pragma unroll
        for (int off = 16; off; off >>= 1) sq += __shfl_xor_sync(0xffffffffu, sq, off);
        if (lane == 0) sfac[wid] = sq / (1.f + sq) / (sqrtf(sq) + 1e-8f);
    }
    __syncthreads();
    for (int i = threadIdx.x; i < NO * NE; i += 256)
        sv[i] *= sfac[i >> 7];
    __syncthreads();

    const float4* svv = (const float4*)sv;
    for (int idx = threadIdx.x; idx < 64 * 192; idx += 256) {
        int l = idx / 192, c = idx % 192;
        out[((size_t)b * NL + lb + l) * 192 + c] = svv[c];
    }
}

// probs broadcast: probs[b,l,k,o] = p[b,k,o].  grid (NB, NL/16), block 256
__global__ void k_out_p(float4* __restrict__ outp) {
    __shared__ float4 spp[NK * NO / 4];  // 1536 float4 = 24 KB
    int b  = blockIdx.x;
    int lb = blockIdx.y * 16;
    const float4* psrc = (const float4*)(g_p + (size_t)b * NK * NO);
    for (int i = threadIdx.x; i < 1536; i += 256) spp[i] = psrc[i];
    __syncthreads();
    for (int l = 0; l < 16; l++) {
        float4* dst = outp + ((size_t)b * NL + lb + l) * 1536;
#pragma unroll 2
        for (int i = threadIdx.x; i < 1536; i += 256) dst[i] = spp[i];
    }
}

// ---------------------------------------------------------------------------
extern "C" void kernel_launch(void* const* d_in, const int* in_sizes, int n_in,
                              void* d_out, int out_size) {
    const float*         u    = (const float*)d_in[0];
    // d_in[1] = context_sequence: unused (result is independent of L content)
    const float*         W    = (const float*)d_in[2];
    const unsigned char* mask = (const unsigned char*)d_in[3];

    float* out   = (float*)d_out;
    float4* outv = (float4*)out;                               // [B,L,O,E]
    float4* outp = (float4*)(out + (size_t)NB * NL * NO * NE); // [B,L,K,O]

    dim3 b256(256);
    dim3 gCS(NB, ND / 256, 16);
    dim3 gS(NO, ND / 16);
    dim3 gWv(NO, ND / 64);
    dim3 gAP(NB, NK / 32);

    // iteration 0: uniform p -> colsum shortcut
    k_prolog<<<192, b256>>>(mask);
    k_colsum<<<gCS, b256>>>(u);
    k_S<1><<<gS, 128>>>(W);
    k_WvSq<<<gWv, b256>>>(W);                   // v0 -> Wv0; zero pu
    k_apu<0><<<gAP, b256>>>(u, mask);           // a=u.Wv0, p1, pu1; zero S

    // iteration 1
    k_S<0><<<gS, 128>>>(W);
    k_WvSq<<<gWv, b256>>>(W);                   // v1 -> Wv1; zero pu
    k_apu<1><<<gAP, b256>>>(u, mask);           // a+=u.Wv1, p2, pu2; zero S

    // iteration 2 (final): v2 from p2
    k_S<0><<<gS, 128>>>(W);

    // outputs: squash fused into v-broadcast; p broadcast
    k_out_v<<<dim3(NB, NL / 64), b256>>>(outv);
    k_out_p<<<dim3(NB, NL / 16), b256>>>(outp);

    (void)in_sizes; (void)n_in; (void)out_size;
}

// round 8
// speedup vs baseline: 1.0045x; 1.0045x over previous
#include <cuda_runtime.h>
#include <math.h>

// Problem constants
#define NB 8
#define NK 1024
#define NL 1024
#define ND 1024
#define NO 6
#define NE 128

// Scratch (tiny): everything l-independent
__device__ __align__(16) float g_S [NB*NO*NE];   // raw vote sum   [b,o,e]
__device__ __align__(16) float g_Wv[NB*NO*ND];   // W @ v          [b,o,d]
__device__ __align__(16) float g_a [NB*NK*NO];   // logits         [b,k,o]
__device__ __align__(16) float g_p [NB*NK*NO];   // probs          [b,k,o]
__device__ __align__(16) float g_pu[NB*NO*ND];   // p^T @ u        [b,o,d]
__device__ int g_mask_is_u8;                     // mask dtype flag

// ---------------------------------------------------------------------------
// Prolog: zero g_pu & g_S, detect mask dtype.
__global__ void k_prolog(const unsigned char* __restrict__ mraw) {
    int i = blockIdx.x * 256 + threadIdx.x;
    if (i < NB*NO*ND) g_pu[i] = 0.f;
    if (i < NB*NO*NE) g_S[i]  = 0.f;
    if (blockIdx.x == 0 && threadIdx.x == 0) {
        int u8 = 0;
        for (int j = 0; j < 256; j++)
            if ((j & 3) != 0 && mraw[j] != 0) u8 = 1;
        g_mask_is_u8 = u8;
    }
}

__device__ __forceinline__ int mask_at(const unsigned char* mraw, size_t idx) {
    if (g_mask_is_u8) return mraw[idx] != 0;
    return ((const int*)mraw)[idx] != 0;
}

// ---------------------------------------------------------------------------
// Iteration-0 shortcut: p0 = 1/6 uniformly, so pu0[b,o,d] = (1/6)*sum_k u —
// o-independent. Compute colsum into g_pu[b][o=0][:].
// grid (NB, ND/256, 16), block 256
__global__ void k_colsum(const float* __restrict__ u) {
    int b  = blockIdx.x;
    int d  = blockIdx.y * 256 + threadIdx.x;
    int kb = blockIdx.z * 64;
    const float* up = u + ((size_t)b * NK + kb) * ND + d;
    float acc = 0.f;
#pragma unroll 8
    for (int kk = 0; kk < 64; kk++) acc += up[(size_t)kk * ND];
    atomicAdd(&g_pu[(size_t)b * NO * ND + d], acc);
}

// ---------------------------------------------------------------------------
// S[b,o,e] += sum_{d in 16-chunk} pu[b,o,d] * W[o,d,e] for all 8 b at once.
// FIRST: read o-independent colsum (o=0 row) scaled by 1/6.
// grid (NO, ND/16), block 128.
template <int FIRST>
__global__ void k_S(const float* __restrict__ W) {
    __shared__ float spu[NB][16];
    int o  = blockIdx.x;
    int dc = blockIdx.y * 16;
    int e  = threadIdx.x;

    {   // 128 threads load exactly 128 entries
        int b = threadIdx.x >> 4, dd = threadIdx.x & 15;
        float v = FIRST ? g_pu[(size_t)b * NO * ND + dc + dd] * (1.f / 6.f)
                        : g_pu[((size_t)b * NO + o) * ND + dc + dd];
        spu[b][dd] = v;
    }
    __syncthreads();

    float acc[NB];
#pragma unroll
    for (int b = 0; b < NB; b++) acc[b] = 0.f;

    const float* Wo = W + ((size_t)o * ND + dc) * NE + e;
#pragma unroll
    for (int dd = 0; dd < 16; dd++) {
        float w = Wo[(size_t)dd * NE];
#pragma unroll
        for (int b = 0; b < NB; b++) acc[b] += spu[b][dd] * w;
    }
#pragma unroll
    for (int b = 0; b < NB; b++)
        atomicAdd(&g_S[((size_t)b * NO + o) * NE + e], acc[b]);
}

// ---------------------------------------------------------------------------
// Fused squash + Wv: warp-per-b, lane-per-d. No shuffles in the dot, 192
// blocks for full-chip coverage. Wv[b,o,d] = sum_e W[o,d,e]*squash(S)[b,o,e].
// Also zeroes g_pu for the next k_apu (192 blocks x 256 floats).
// grid (NO, ND/32), block 256 = 8 warps (warp = b), lane = d within chunk.
__global__ void k_WvSq(const float* __restrict__ W) {
    __shared__ float sW[32][NE + 1];  // 16.5 KB, stride 129 -> conflict-free
    __shared__ float sv[NB][NE];      // 4 KB
    __shared__ float sfac[NB];
    int o  = blockIdx.x;
    int db = blockIdx.y * 32;
    int wid = threadIdx.x >> 5, lane = threadIdx.x & 31;

    // zero g_pu slice: 49152 / 192 blocks = 256 floats per block
    {
        int slice = blockIdx.x * (ND / 32) + blockIdx.y;   // 0..191
        g_pu[(size_t)slice * 256 + threadIdx.x] = 0.f;
    }

    // stage W tile [32 d][128 e] (coalesced) and S
    for (int i = threadIdx.x; i < 32 * NE; i += 256) {
        int d = i >> 7, e = i & 127;
        sW[d][e] = W[((size_t)o * ND + db + d) * NE + e];
    }
    for (int i = threadIdx.x; i < NB * NE; i += 256)
        sv[i >> 7][i & 127] = g_S[((size_t)(i >> 7) * NO + o) * NE + (i & 127)];
    __syncthreads();

    // squash factor: warp w computes factor for b=w
    {
        float sq = 0.f;
#pragma unroll
        for (int j = 0; j < 4; j++) {
            float x = sv[wid][lane + 32 * j];
            sq += x * x;
        }
#pragma unroll
        for (int off = 16; off; off >>= 1) sq += __shfl_xor_sync(0xffffffffu, sq, off);
        if (lane == 0) sfac[wid] = sq / (1.f + sq) / (sqrtf(sq) + 1e-8f);
    }
    __syncthreads();
    for (int i = threadIdx.x; i < NB * NE; i += 256)
        sv[i >> 7][i & 127] *= sfac[i >> 7];
    __syncthreads();

    // warp wid -> b=wid; lane -> d=db+lane. Full e-dot, 4 accumulators.
    float a0 = 0.f, a1 = 0.f, a2 = 0.f, a3 = 0.f;
#pragma unroll
    for (int e = 0; e < NE; e += 4) {
        a0 += sW[lane][e    ] * sv[wid][e    ];
        a1 += sW[lane][e + 1] * sv[wid][e + 1];
        a2 += sW[lane][e + 2] * sv[wid][e + 2];
        a3 += sW[lane][e + 3] * sv[wid][e + 3];
    }
    g_Wv[((size_t)wid * NO + o) * ND + db + lane] = (a0 + a1) + (a2 + a3);
}

// ---------------------------------------------------------------------------
// Fused agreement + softmax + pu-accumulation:
//  phase 1: a[b,k,o] (+)= sum_d u[b,k,d]*Wv[b,o,d]; p = masked softmax (->smem+g_p)
//  phase 2: pu[b,o,d] += sum_{k in block} p[k,o]*u[b,k,d]  (u rows hot in L1/L2)
// Also zeroes g_S slices for the next k_S.
// grid (NB, NK/32), block 256 = 8 warps, each warp does 4 k's.
template <int ACCUM>
__global__ void k_apu(const float* __restrict__ u,
                      const unsigned char* __restrict__ mraw) {
    __shared__ float sWv[NO * ND];  // 24 KB
    __shared__ float sp[32][NO];
    int b  = blockIdx.x;
    int kb = blockIdx.y * 32;

    // zero g_S slice: 6144 / 256 blocks = 24 floats each
    {
        int slice = blockIdx.x * 32 + blockIdx.y;   // 0..255
        if (threadIdx.x < 24) g_S[(size_t)slice * 24 + threadIdx.x] = 0.f;
    }

    for (int i = threadIdx.x; i < NO * ND; i += 256)
        sWv[i] = g_Wv[(size_t)b * NO * ND + i];
    __syncthreads();

    int warp = threadIdx.x >> 5, lane = threadIdx.x & 31;

    for (int ki = 0; ki < 4; ki++) {
        int k = kb + warp * 4 + ki;
        const float* urow = u + ((size_t)b * NK + k) * ND;
        float a0 = 0, a1 = 0, a2 = 0, a3 = 0, a4 = 0, a5 = 0;
#pragma unroll 4
        for (int j = 0; j < 32; j++) {
            int d = lane + 32 * j;
            float uv = urow[d];
            a0 += uv * sWv[d];
            a1 += uv * sWv[ND + d];
            a2 += uv * sWv[2 * ND + d];
            a3 += uv * sWv[3 * ND + d];
            a4 += uv * sWv[4 * ND + d];
            a5 += uv * sWv[5 * ND + d];
        }
#pragma unroll
        for (int off = 16; off; off >>= 1) {
            a0 += __shfl_xor_sync(0xffffffffu, a0, off);
            a1 += __shfl_xor_sync(0xffffffffu, a1, off);
            a2 += __shfl_xor_sync(0xffffffffu, a2, off);
            a3 += __shfl_xor_sync(0xffffffffu, a3, off);
            a4 += __shfl_xor_sync(0xffffffffu, a4, off);
            a5 += __shfl_xor_sync(0xffffffffu, a5, off);
        }
        if (lane == 0) {
            float av[NO] = {a0, a1, a2, a3, a4, a5};
            size_t base = ((size_t)b * NK + k) * NO;
            if (ACCUM) {
#pragma unroll
                for (int o = 0; o < NO; o++) av[o] += g_a[base + o];
            }
#pragma unroll
            for (int o = 0; o < NO; o++) g_a[base + o] = av[o];

            float pr[NO];
            if (mask_at(mraw, (size_t)b * NK + k)) {
#pragma unroll
                for (int o = 0; o < NO; o++) pr[o] = 1.f / 6.f;
            } else {
                float m = av[0];
#pragma unroll
                for (int o = 1; o < NO; o++) m = fmaxf(m, av[o]);
                float ssum = 0.f;
#pragma unroll
                for (int o = 0; o < NO; o++) { pr[o] = expf(av[o] - m); ssum += pr[o]; }
                float inv = 1.f / ssum;
#pragma unroll
                for (int o = 0; o < NO; o++) pr[o] *= inv;
            }
#pragma unroll
            for (int o = 0; o < NO; o++) {
                g_p[base + o] = pr[o];
                sp[warp * 4 + ki][o] = pr[o];
            }
        }
    }
    __syncthreads();

    // phase 2: pu accumulation over this block's 32 k rows
#pragma unroll
    for (int dj = 0; dj < 4; dj++) {
        int d = dj * 256 + threadIdx.x;
        const float* ucol = u + ((size_t)b * NK + kb) * ND + d;
        float acc[NO];
#pragma unroll
        for (int o = 0; o < NO; o++) acc[o] = 0.f;
#pragma unroll 4
        for (int kk = 0; kk < 32; kk++) {
            float uv = ucol[(size_t)kk * ND];
#pragma unroll
            for (int o = 0; o < NO; o++) acc[o] += sp[kk][o] * uv;
        }
#pragma unroll
        for (int o = 0; o < NO; o++)
            atomicAdd(&g_pu[((size_t)b * NO + o) * ND + d], acc[o]);
    }
}

// ---------------------------------------------------------------------------
// Final: squash(S) fused with the L-broadcast of outputs_v.
// outputs_v[b,l,o,e] = squash(S)[b,o,e].  grid (NB, NL/16), block 256
__global__ void k_out_v(float4* __restrict__ out) {
    __shared__ __align__(16) float sv[NO * NE];  // 768 floats
    __shared__ float sfac[NO];
    int b  = blockIdx.x;
    int lb = blockIdx.y * 16;
    int wid = threadIdx.x >> 5, lane = threadIdx.x & 31;

    for (int i = threadIdx.x; i < NO * NE; i += 256)
        sv[i] = g_S[(size_t)b * NO * NE + i];
    __syncthreads();

    if (wid < NO) {
        float sq = 0.f;
#pragma unroll
        for (int j = 0; j < 4; j++) {
            float x = sv[wid * NE + lane + 32 * j];
            sq += x * x;
        }
#pragma unroll
        for (int off = 16; off; off >>= 1) sq += __shfl_xor_sync(0xffffffffu, sq, off);
        if (lane == 0) sfac[wid] = sq / (1.f + sq) / (sqrtf(sq) + 1e-8f);
    }
    __syncthreads();
    for (int i = threadIdx.x; i < NO * NE; i += 256)
        sv[i] *= sfac[i >> 7];
    __syncthreads();

    const float4* svv = (const float4*)sv;
    for (int l = 0; l < 16; l++) {
        float4* dst = out + ((size_t)b * NL + lb + l) * 192;
        if (threadIdx.x < 192) dst[threadIdx.x] = svv[threadIdx.x];
    }
}

// probs broadcast: probs[b,l,k,o] = p[b,k,o].  grid (NB, NL/16), block 256
__global__ void k_out_p(float4* __restrict__ outp) {
    __shared__ float4 spp[NK * NO / 4];  // 1536 float4 = 24 KB
    int b  = blockIdx.x;
    int lb = blockIdx.y * 16;
    const float4* psrc = (const float4*)(g_p + (size_t)b * NK * NO);
    for (int i = threadIdx.x; i < 1536; i += 256) spp[i] = psrc[i];
    __syncthreads();
    for (int l = 0; l < 16; l++) {
        float4* dst = outp + ((size_t)b * NL + lb + l) * 1536;
#pragma unroll 2
        for (int i = threadIdx.x; i < 1536; i += 256) dst[i] = spp[i];
    }
}

// ---------------------------------------------------------------------------
extern "C" void kernel_launch(void* const* d_in, const int* in_sizes, int n_in,
                              void* d_out, int out_size) {
    const float*         u    = (const float*)d_in[0];
    // d_in[1] = context_sequence: unused (result is independent of L content)
    const float*         W    = (const float*)d_in[2];
    const unsigned char* mask = (const unsigned char*)d_in[3];

    float* out   = (float*)d_out;
    float4* outv = (float4*)out;                               // [B,L,O,E]
    float4* outp = (float4*)(out + (size_t)NB * NL * NO * NE); // [B,L,K,O]

    dim3 b256(256);
    dim3 gCS(NB, ND / 256, 16);
    dim3 gS(NO, ND / 16);
    dim3 gWv(NO, ND / 32);
    dim3 gAP(NB, NK / 32);

    // iteration 0: uniform p -> colsum shortcut
    k_prolog<<<192, b256>>>(mask);
    k_colsum<<<gCS, b256>>>(u);
    k_S<1><<<gS, 128>>>(W);
    k_WvSq<<<gWv, b256>>>(W);                   // v0 -> Wv0; zero pu
    k_apu<0><<<gAP, b256>>>(u, mask);           // a=u.Wv0, p1, pu1; zero S

    // iteration 1
    k_S<0><<<gS, 128>>>(W);
    k_WvSq<<<gWv, b256>>>(W);                   // v1 -> Wv1; zero pu
    k_apu<1><<<gAP, b256>>>(u, mask);           // a+=u.Wv1, p2, pu2; zero S

    // iteration 2 (final): v2 from p2
    k_S<0><<<gS, 128>>>(W);

    // outputs: squash fused into v-broadcast; p broadcast
    k_out_v<<<dim3(NB, NL / 16), b256>>>(outv);
    k_out_p<<<dim3(NB, NL / 16), b256>>>(outp);

    (void)in_sizes; (void)n_in; (void)out_size;
}